// round 9
// baseline (speedup 1.0000x reference)
#include <cuda_runtime.h>
#include <cuda_fp16.h>
#include <cstdint>

#define D_IN   128
#define HID    512
#define D_OUTK 128
#define NOBJ   100000
#define NT     200000

#define BM 128
#define BN 128
#define BK 64                      // halfs per stage-chunk (128 B per row)
#define A_BYTES (BM * BK * 2)      // 16 KB
#define STAGE_BYTES (2 * A_BYTES)  // A + B = 32 KB
#define NSTAGE 3
#define SMEMB (NSTAGE * STAGE_BYTES)
#define NTHREADS 128

// Scratch (device globals — no allocation allowed)
__device__ __align__(16) __half g_h[(size_t)NT * HID];
__device__ __align__(16) float  g_pooled[(size_t)NOBJ * HID];
__device__ __align__(16) __half g_pooledh[(size_t)NOBJ * HID];
__device__ __align__(16) __half g_tmph[(size_t)NOBJ * HID];
__device__ __align__(16) float  g_counts[NOBJ];
__device__ __align__(16) __half g_objth[(size_t)NOBJ * D_IN];
__device__ __align__(16) __half g_predth[(size_t)NT * D_IN];
// Weights transposed to [n][k], fp16
__device__ __align__(16) __half g_W1T[(size_t)HID * 384];
__device__ __align__(16) __half g_W2T[(size_t)1152 * HID];
__device__ __align__(16) __half g_W3T[(size_t)HID * HID];
__device__ __align__(16) __half g_W4T[(size_t)D_OUTK * HID];

// ---------------------------------------------------------------------------
__device__ __forceinline__ void mma_f16(float* c, const uint32_t* a, const uint32_t* b) {
    asm volatile(
        "mma.sync.aligned.m16n8k16.row.col.f32.f16.f16.f32 "
        "{%0,%1,%2,%3}, {%4,%5,%6,%7}, {%8,%9}, {%0,%1,%2,%3};"
        : "+f"(c[0]), "+f"(c[1]), "+f"(c[2]), "+f"(c[3])
        : "r"(a[0]), "r"(a[1]), "r"(a[2]), "r"(a[3]), "r"(b[0]), "r"(b[1]));
}

__device__ __forceinline__ void ldsm4(uint32_t& r0, uint32_t& r1, uint32_t& r2,
                                      uint32_t& r3, uint32_t addr) {
    asm volatile("ldmatrix.sync.aligned.m8n8.x4.shared.b16 {%0,%1,%2,%3}, [%4];"
                 : "=r"(r0), "=r"(r1), "=r"(r2), "=r"(r3) : "r"(addr));
}

__device__ __forceinline__ void cp16(uint32_t d, const void* s, int sz) {
    asm volatile("cp.async.cg.shared.global [%0], [%1], 16, %2;"
                 :: "r"(d), "l"(s), "r"(sz));
}
#define CP_COMMIT() asm volatile("cp.async.commit_group;" ::: "memory")
#define CP_WAIT1()  asm volatile("cp.async.wait_group 1;" ::: "memory")

__device__ __forceinline__ void red_add_v2(float* addr, float x, float y) {
    asm volatile("red.global.add.v2.f32 [%0], {%1, %2};"
                 :: "l"(addr), "f"(x), "f"(y) : "memory");
}

// ---------------------------------------------------------------------------
__global__ void zero_counts() {
    int i = blockIdx.x * blockDim.x + threadIdx.x;
    if (i < NOBJ) g_counts[i] = 0.f;
}

// Section-dispatched prep: pooled zero | cvt obj | cvt pred | cvtT W1-4 | count
#define NB_POOL  50000
#define NB_OBJ   12500
#define NB_PRED  25000
#define NB_W1    768
#define NB_W2    2304
#define NB_W3    1024
#define NB_W4    256
#define NB_CNT   782
#define NB_TOTAL (NB_POOL + NB_OBJ + NB_PRED + NB_W1 + NB_W2 + NB_W3 + NB_W4 + NB_CNT)

__device__ __forceinline__ void cvt_sec(const float* src, __half* dst, int i) {
    float4 v = ((const float4*)src)[i];
    __half2* d2 = (__half2*)dst;
    d2[2 * i]     = __floats2half2_rn(v.x, v.y);
    d2[2 * i + 1] = __floats2half2_rn(v.z, v.w);
}
__device__ __forceinline__ void cvtT_sec(const float* W, __half* WT, int K, int N, int idx) {
    int n = idx / K, k = idx - n * K;
    WT[idx] = __float2half_rn(W[(size_t)k * N + n]);
}

__global__ void prep_kernel(const float* __restrict__ obj, const float* __restrict__ pred,
                            const int* __restrict__ edges,
                            const float* __restrict__ W1, const float* __restrict__ W2,
                            const float* __restrict__ W3, const float* __restrict__ W4)
{
    int b = blockIdx.x;
    int t = threadIdx.x;
    if (b < NB_POOL) {
        int i = b * 256 + t;
        ((float4*)g_pooled)[i] = make_float4(0.f, 0.f, 0.f, 0.f);
        return;
    }
    b -= NB_POOL;
    if (b < NB_OBJ)  { cvt_sec(obj,  g_objth,  b * 256 + t); return; }
    b -= NB_OBJ;
    if (b < NB_PRED) { cvt_sec(pred, g_predth, b * 256 + t); return; }
    b -= NB_PRED;
    if (b < NB_W1) { cvtT_sec(W1, g_W1T, 384, 512,  b * 256 + t); return; }
    b -= NB_W1;
    if (b < NB_W2) { cvtT_sec(W2, g_W2T, 512, 1152, b * 256 + t); return; }
    b -= NB_W2;
    if (b < NB_W3) { cvtT_sec(W3, g_W3T, 512, 512,  b * 256 + t); return; }
    b -= NB_W3;
    if (b < NB_W4) { cvtT_sec(W4, g_W4T, 512, 128,  b * 256 + t); return; }
    b -= NB_W4;
    {
        int e = b * 256 + t;
        if (e < NT) {
            atomicAdd(&g_counts[edges[2 * e]],     1.f);
            atomicAdd(&g_counts[edges[2 * e + 1]], 1.f);
        }
    }
}

__global__ void normalize_h() {
    int i = blockIdx.x * blockDim.x + threadIdx.x;
    if (i < (NOBJ * HID) / 4) {
        int r = i >> 7;
        float sc = 1.f / fmaxf(g_counts[r], 1.f);
        float4 v = ((const float4*)g_pooled)[i];
        __half2* d2 = (__half2*)g_pooledh;
        d2[2 * i]     = __floats2half2_rn(v.x * sc, v.y * sc);
        d2[2 * i + 1] = __floats2half2_rn(v.z * sc, v.w * sc);
    }
}

// ---------------------------------------------------------------------------
// 128 threads = 4 warps in 2(m) x 2(n); warp tile 64x64.
// KIND 0: g_h    = h(relu(gather @ W1T + b1))        M=NT,   K=384, N=512
// KIND 1: scatter/out_p from relu(g_h @ W2T + b2)    M=NT,   K=512, N=1152
// KIND 2: g_tmph = h(relu(pooledh @ W3T + b3))       M=NOBJ, K=512, N=512
// KIND 3: out_obj = relu(g_tmph @ W4T + b4)          M=NOBJ, K=512, N=128
template<int KIND>
__global__ void __launch_bounds__(NTHREADS, 2) hgemm(const int* __restrict__ edges,
                                                     const float* __restrict__ bias,
                                                     float* __restrict__ out, int M)
{
    constexpr int K  = (KIND == 0) ? 384 : 512;
    constexpr int KT = K / BK;
    extern __shared__ __align__(16) char sh[];
    uint32_t sm = (uint32_t)__cvta_generic_to_shared(sh);

    int tid = threadIdx.x, lane = tid & 31, w = tid >> 5;
    int wm = w & 1, wn = w >> 1;                 // 2 (m) x 2 (n) warps
    int gr = lane >> 2, ct = lane & 3;
    int sel = lane >> 3, lr = lane & 7;          // ldmatrix lane roles
    int row0 = blockIdx.y * BM;
    int col0 = blockIdx.x * BN;

    int mode = 0, pcol = 0;                      // KIND 1 column routing
    if (KIND == 1) {
        int bx = blockIdx.x;
        if (bx < 4)       { mode = 0; pcol = bx * 128; }
        else if (bx == 4) { mode = 1; pcol = 0; }
        else              { mode = 2; pcol = (bx - 5) * 128; }
    }

    const __half* Wt   = (KIND == 0) ? g_W1T : (KIND == 1) ? g_W2T
                       : (KIND == 2) ? g_W3T : g_W4T;
    const __half* Amat = (KIND == 1) ? g_h : (KIND == 2) ? g_pooledh : g_tmph;

    float acc[4][8][4];
#pragma unroll
    for (int i = 0; i < 4; i++)
#pragma unroll
        for (int j = 0; j < 8; j++)
#pragma unroll
            for (int k = 0; k < 4; k++) acc[i][j][k] = 0.f;

    auto load_stage = [&](int kt) {
        int k0 = kt * BK;                          // in halfs
        uint32_t ab = sm + (uint32_t)(kt % NSTAGE) * STAGE_BYTES;
        uint32_t bb = ab + A_BYTES;
#pragma unroll
        for (int i = 0; i < 8; i++) {              // A: 128 rows x 8 chunks
            int f = tid + i * NTHREADS;
            int m = f >> 3, ch = f & 7;
            int mg = row0 + m;
            int sz = (mg < M) ? 16 : 0;
            int mc = (mg < M) ? mg : M - 1;
            const char* src;
            if (KIND == 0) {
                int region = k0 >> 7;
                int bo = (k0 & 127) * 2;
                if (region == 0)      src = (const char*)(g_objth  + (size_t)edges[2 * mc]     * 128) + bo;
                else if (region == 1) src = (const char*)(g_predth + (size_t)mc                * 128) + bo;
                else                  src = (const char*)(g_objth  + (size_t)edges[2 * mc + 1] * 128) + bo;
            } else {
                src = (const char*)(Amat + (size_t)mc * K + k0);
            }
            cp16(ab + (uint32_t)(m * 128 + ((ch ^ (m & 7)) * 16)), src + ch * 16, sz);
        }
#pragma unroll
        for (int i = 0; i < 8; i++) {              // B: 128 n-rows x 8 chunks
            int f = tid + i * NTHREADS;
            int n = f >> 3, ch = f & 7;
            const char* src = (const char*)(Wt + (size_t)(col0 + n) * K + k0) + ch * 16;
            cp16(bb + (uint32_t)(n * 128 + ((ch ^ (n & 7)) * 16)), src, 16);
        }
    };

    int a_row[4];
#pragma unroll
    for (int mf = 0; mf < 4; mf++)
        a_row[mf] = wm * 64 + mf * 16 + lr + ((sel & 1) << 3);
    int b_row[4];
#pragma unroll
    for (int p = 0; p < 4; p++)
        b_row[p] = wn * 64 + p * 16 + lr + ((sel >> 1) << 3);

    auto mma_stage = [&](int b) {
        uint32_t abase = sm + (uint32_t)b * STAGE_BYTES;
        uint32_t bbase = abase + A_BYTES;
#pragma unroll
        for (int kb = 0; kb < BK / 16; kb++) {
            uint32_t a[4][4], bf[8][2];
            int a_ch = 2 * kb + (sel >> 1);
#pragma unroll
            for (int mf = 0; mf < 4; mf++) {
                int r = a_row[mf];
                uint32_t addr = abase + (uint32_t)(r * 128 + ((a_ch ^ (r & 7)) * 16));
                ldsm4(a[mf][0], a[mf][1], a[mf][2], a[mf][3], addr);
            }
            int b_ch = 2 * kb + (sel & 1);
#pragma unroll
            for (int p = 0; p < 4; p++) {
                int r = b_row[p];
                uint32_t addr = bbase + (uint32_t)(r * 128 + ((b_ch ^ (r & 7)) * 16));
                ldsm4(bf[2 * p][0], bf[2 * p][1], bf[2 * p + 1][0], bf[2 * p + 1][1], addr);
            }
#pragma unroll
            for (int mf = 0; mf < 4; mf++)
#pragma unroll
                for (int nf = 0; nf < 8; nf++)
                    mma_f16(acc[mf][nf], a[mf], bf[nf]);
        }
    };

    load_stage(0); CP_COMMIT();
    load_stage(1); CP_COMMIT();

    for (int kt = 0; kt < KT; kt++) {
        CP_WAIT1();
        __syncthreads();
        if (kt + 2 < KT) load_stage(kt + 2);
        CP_COMMIT();
        mma_stage(kt % NSTAGE);
    }

    // ---- epilogue ----
    float bb[8][2];
#pragma unroll
    for (int nf = 0; nf < 8; nf++) {
        int c = col0 + wn * 64 + nf * 8 + ct * 2;
        bb[nf][0] = bias[c]; bb[nf][1] = bias[c + 1];
    }

#pragma unroll
    for (int mf = 0; mf < 4; mf++)
#pragma unroll
        for (int half = 0; half < 2; half++) {
            int r = row0 + wm * 64 + mf * 16 + gr + half * 8;
            if (r >= M) continue;
            int cbase = wn * 64 + ct * 2;
            if (KIND == 0 || KIND == 2) {
                __half* dst = ((KIND == 0) ? g_h : g_tmph) + (size_t)r * HID + col0 + cbase;
#pragma unroll
                for (int nf = 0; nf < 8; nf++) {
                    float x = fmaxf(acc[mf][nf][half * 2 + 0] + bb[nf][0], 0.f);
                    float y = fmaxf(acc[mf][nf][half * 2 + 1] + bb[nf][1], 0.f);
                    *(__half2*)(dst + nf * 8) = __floats2half2_rn(x, y);
                }
            } else if (KIND == 3) {
                float* dst = out + (size_t)r * D_OUTK + cbase;
#pragma unroll
                for (int nf = 0; nf < 8; nf++) {
                    float2 o;
                    o.x = fmaxf(acc[mf][nf][half * 2 + 0] + bb[nf][0], 0.f);
                    o.y = fmaxf(acc[mf][nf][half * 2 + 1] + bb[nf][1], 0.f);
                    *(float2*)(dst + nf * 8) = o;
                }
            } else {  // KIND == 1
                if (mode == 1) {
                    float* dst = out + (size_t)r * D_OUTK + cbase;
#pragma unroll
                    for (int nf = 0; nf < 8; nf++) {
                        float2 o;
                        o.x = fmaxf(acc[mf][nf][half * 2 + 0] + bb[nf][0], 0.f);
                        o.y = fmaxf(acc[mf][nf][half * 2 + 1] + bb[nf][1], 0.f);
                        *(float2*)(dst + nf * 8) = o;
                    }
                } else {
                    int sidx = (mode == 0) ? edges[2 * r] : edges[2 * r + 1];
                    float* dst = g_pooled + (size_t)sidx * HID + pcol + cbase;
#pragma unroll
                    for (int nf = 0; nf < 8; nf++) {
                        float x = fmaxf(acc[mf][nf][half * 2 + 0] + bb[nf][0], 0.f);
                        float y = fmaxf(acc[mf][nf][half * 2 + 1] + bb[nf][1], 0.f);
                        red_add_v2(dst + nf * 8, x, y);
                    }
                }
            }
        }
}

// ---------------------------------------------------------------------------
extern "C" void kernel_launch(void* const* d_in, const int* in_sizes, int n_in,
                              void* d_out, int out_size)
{
    const float* obj   = (const float*)d_in[0];
    const float* pred  = (const float*)d_in[1];
    const int*   edges = (const int*)  d_in[2];
    const float* W1 = (const float*)d_in[3];
    const float* b1 = (const float*)d_in[4];
    const float* W2 = (const float*)d_in[5];
    const float* b2 = (const float*)d_in[6];
    const float* W3 = (const float*)d_in[7];
    const float* b3 = (const float*)d_in[8];
    const float* W4 = (const float*)d_in[9];
    const float* b4 = (const float*)d_in[10];

    float* out     = (float*)d_out;
    float* out_obj = out;                           // (NOBJ, 128)
    float* out_p   = out + (size_t)NOBJ * D_OUTK;   // (NT, 128)

    cudaFuncSetAttribute(hgemm<0>, cudaFuncAttributeMaxDynamicSharedMemorySize, SMEMB);
    cudaFuncSetAttribute(hgemm<1>, cudaFuncAttributeMaxDynamicSharedMemorySize, SMEMB);
    cudaFuncSetAttribute(hgemm<2>, cudaFuncAttributeMaxDynamicSharedMemorySize, SMEMB);
    cudaFuncSetAttribute(hgemm<3>, cudaFuncAttributeMaxDynamicSharedMemorySize, SMEMB);

    zero_counts<<<(NOBJ + 255) / 256, 256>>>();
    prep_kernel<<<NB_TOTAL, 256>>>(obj, pred, edges, W1, W2, W3, W4);

    int gy_t = (NT + BM - 1) / BM;    // 1563
    int gy_o = (NOBJ + BM - 1) / BM;  // 782

    hgemm<0><<<dim3(4, gy_t), NTHREADS, SMEMB>>>(edges, b1, nullptr, NT);
    hgemm<1><<<dim3(9, gy_t), NTHREADS, SMEMB>>>(edges, b2, out_p, NT);
    normalize_h<<<(NOBJ * HID / 4 + 255) / 256, 256>>>();
    hgemm<2><<<dim3(4, gy_o), NTHREADS, SMEMB>>>(edges, b3, nullptr, NOBJ);
    hgemm<3><<<dim3(1, gy_o), NTHREADS, SMEMB>>>(edges, b4, out_obj, NOBJ);
}